// round 4
// baseline (speedup 1.0000x reference)
#include <cuda_runtime.h>

#define N_NODES 100000
#define N_EDGES 1600000
#define SCAN_BLOCKS 98   // ceil(100000/1024)

// ---------------- scratch (static __device__ allocations; no cudaMalloc) ----
__device__ float g_y[(size_t)N_NODES * 128];   // (A@W)*dinv buffer
__device__ float g_h[(size_t)N_NODES * 128];   // post-aggregate hidden buffer
__device__ int   g_cnt[N_NODES];
__device__ int   g_rowptr[N_NODES + 1];
__device__ int   g_cursor[N_NODES];
__device__ float g_dinv[N_NODES];
__device__ int   g_csr[N_EDGES];
__device__ int   g_bsums[SCAN_BLOCKS];
__device__ int   g_is64;

// ---------------- helpers ---------------------------------------------------
__device__ __forceinline__ float4 f4add(float4 a, float4 b) {
    return make_float4(a.x + b.x, a.y + b.y, a.z + b.z, a.w + b.w);
}

// Fetch (src, dst) of edge e, supporting int32 (expected) or int64 layout.
__device__ __forceinline__ void edge_fetch(const int* __restrict__ ei, int e,
                                           int& src, int& dst, int is64) {
    if (is64) {
        src = ei[2 * e];
        dst = ei[2 * (N_EDGES + e)];
    } else {
        src = ei[e];
        dst = ei[N_EDGES + e];
    }
}

// ---------------- dtype detection -------------------------------------------
// int64 layout: every odd 32-bit word is the high half of a small positive
// int64 => 0. int32 layout: odd words are random node ids; 64 consecutive
// zeros is impossible for random data.
__global__ void k_detect(const int* __restrict__ ei) {
    if (threadIdx.x == 0) {
        int acc = 0;
        for (int i = 0; i < 64; i++) acc |= ei[2 * i + 1];
        g_is64 = (acc == 0) ? 1 : 0;
    }
}

// ---------------- CSR construction ------------------------------------------
__global__ void k_init() {
    int i = blockIdx.x * blockDim.x + threadIdx.x;
    if (i < N_NODES) g_cnt[i] = 0;
}

__global__ void k_hist(const int* __restrict__ ei) {
    int e = blockIdx.x * blockDim.x + threadIdx.x;
    if (e < N_EDGES) {
        int src, dst;
        edge_fetch(ei, e, src, dst, g_is64);
        if ((unsigned)dst < N_NODES) atomicAdd(&g_cnt[dst], 1);
    }
}

__global__ void k_scan1() {
    __shared__ int sm[1024];
    int i = blockIdx.x * 1024 + threadIdx.x;
    int v = (i < N_NODES) ? g_cnt[i] : 0;
    sm[threadIdx.x] = v;
    __syncthreads();
#pragma unroll
    for (int off = 1; off < 1024; off <<= 1) {
        int t = (threadIdx.x >= off) ? sm[threadIdx.x - off] : 0;
        __syncthreads();
        sm[threadIdx.x] += t;
        __syncthreads();
    }
    int incl = sm[threadIdx.x];
    if (i < N_NODES) g_rowptr[i] = incl - v;     // block-local exclusive
    if (threadIdx.x == 1023) g_bsums[blockIdx.x] = incl;
}

__global__ void k_scan2() {
    if (threadIdx.x == 0) {
        int run = 0;
        for (int b = 0; b < SCAN_BLOCKS; b++) {
            int v = g_bsums[b];
            g_bsums[b] = run;
            run += v;
        }
    }
}

__global__ void k_scan3() {
    int i = blockIdx.x * 1024 + threadIdx.x;
    if (i < N_NODES) {
        int rp = g_rowptr[i] + g_bsums[blockIdx.x];
        g_rowptr[i] = rp;
        g_cursor[i] = rp;
        g_dinv[i] = rsqrtf((float)(g_cnt[i] + 1));  // +1 self-loop
    }
    if (i == 0) g_rowptr[N_NODES] = N_EDGES;
}

__global__ void k_fill(const int* __restrict__ ei) {
    int e = blockIdx.x * blockDim.x + threadIdx.x;
    if (e < N_EDGES) {
        int src, dst;
        edge_fetch(ei, e, src, dst, g_is64);
        if ((unsigned)dst < N_NODES && (unsigned)src < N_NODES) {
            int pos = atomicAdd(&g_cursor[dst], 1);
            g_csr[pos] = src;
        }
    }
}

// ---------------- GEMM: out[row][c] = sum_k A[row][k] * W[k][c] -------------
// 256 threads/block, 8 warps, warp handles 8 rows, lane handles 4 cols.
// SRC: 0 = A param, 1 = g_h (device global)
// MODE: 0 = scale by dinv, write g_y; 1 = FC head: relu(+bias), dot w2 -> out
template <int SRC, int MODE, int KCH>
__global__ void __launch_bounds__(256) k_gemm(
    const float* __restrict__ A, const float* __restrict__ A2,
    const float* __restrict__ W,
    const float* __restrict__ bias, const float* __restrict__ w2,
    const float* __restrict__ w2b, float* __restrict__ out)
{
    const int lane = threadIdx.x & 31;
    const int warp = threadIdx.x >> 5;
    const int row0 = (blockIdx.x * 8 + warp) * 8;
    const int c4 = lane * 4;

    const float* __restrict__ Abase = (SRC == 0) ? A : (const float*)g_h;

    int rc[8];
#pragma unroll
    for (int r = 0; r < 8; r++) {
        int row = row0 + r;
        rc[r] = (row < N_NODES) ? row : (N_NODES - 1);
    }

    float4 acc[8];
#pragma unroll
    for (int r = 0; r < 8; r++) acc[r] = make_float4(0.f, 0.f, 0.f, 0.f);

#pragma unroll 2
    for (int kc = 0; kc < KCH; kc++) {
        const int k = kc * 4;
        float4 w0 = __ldg((const float4*)(W + (size_t)(k + 0) * 128 + c4));
        float4 w1 = __ldg((const float4*)(W + (size_t)(k + 1) * 128 + c4));
        float4 w2v = __ldg((const float4*)(W + (size_t)(k + 2) * 128 + c4));
        float4 w3 = __ldg((const float4*)(W + (size_t)(k + 3) * 128 + c4));
#pragma unroll
        for (int r = 0; r < 8; r++) {
            float4 av;
            if (MODE == 1) {
                if (k < 128)
                    av = __ldg((const float4*)(Abase + (size_t)rc[r] * 128 + k));
                else
                    av = __ldg((const float4*)(A2 + (size_t)rc[r] * 16 + (k - 128)));
            } else {
                av = __ldg((const float4*)(Abase + (size_t)rc[r] * 128 + k));
            }
            acc[r].x += av.x * w0.x + av.y * w1.x + av.z * w2v.x + av.w * w3.x;
            acc[r].y += av.x * w0.y + av.y * w1.y + av.z * w2v.y + av.w * w3.y;
            acc[r].z += av.x * w0.z + av.y * w1.z + av.z * w2v.z + av.w * w3.z;
            acc[r].w += av.x * w0.w + av.y * w1.w + av.z * w2v.w + av.w * w3.w;
        }
    }

    if (MODE == 0) {
#pragma unroll
        for (int r = 0; r < 8; r++) {
            int row = row0 + r;
            if (row < N_NODES) {
                float s = g_dinv[row];
                float4 o = make_float4(acc[r].x * s, acc[r].y * s,
                                       acc[r].z * s, acc[r].w * s);
                *(float4*)(g_y + (size_t)row * 128 + c4) = o;
            }
        }
    } else {
        float4 b4 = __ldg((const float4*)(bias + c4));
        float4 wv = __ldg((const float4*)(w2 + c4));
        float ob = __ldg(w2b);
#pragma unroll
        for (int r = 0; r < 8; r++) {
            float hx = fmaxf(acc[r].x + b4.x, 0.f);
            float hy = fmaxf(acc[r].y + b4.y, 0.f);
            float hz = fmaxf(acc[r].z + b4.z, 0.f);
            float hw = fmaxf(acc[r].w + b4.w, 0.f);
            float p = hx * wv.x + hy * wv.y + hz * wv.z + hw * wv.w;
            p += __shfl_xor_sync(0xFFFFFFFFu, p, 16);
            p += __shfl_xor_sync(0xFFFFFFFFu, p, 8);
            p += __shfl_xor_sync(0xFFFFFFFFu, p, 4);
            p += __shfl_xor_sync(0xFFFFFFFFu, p, 2);
            p += __shfl_xor_sync(0xFFFFFFFFu, p, 1);
            int row = row0 + r;
            if (lane == 0 && row < N_NODES) out[row] = p + ob;
        }
    }
}

// ---------------- gather-aggregate: one warp per dst row --------------------
// g_h[i][c] = relu( dinv[i] * ( g_y[i][c] + sum_{src in in(i)} g_y[src][c] ) + b[c] )
__global__ void __launch_bounds__(256) k_aggregate(
    const float* __restrict__ bias)
{
    const int lane = threadIdx.x & 31;
    const int warp = threadIdx.x >> 5;
    const int row = blockIdx.x * 8 + warp;
    if (row >= N_NODES) return;

    const int s = g_rowptr[row];
    const int e = g_rowptr[row + 1];
    const float4* yv = (const float4*)g_y;

    float4 a0 = __ldg(&yv[(size_t)row * 32 + lane]);  // self-loop term
    float4 a1 = make_float4(0.f, 0.f, 0.f, 0.f);
    float4 a2 = a1, a3 = a1;

    int i = s;
    for (; i + 4 <= e; i += 4) {
        int i0 = g_csr[i + 0];
        int i1 = g_csr[i + 1];
        int i2 = g_csr[i + 2];
        int i3 = g_csr[i + 3];
        a0 = f4add(a0, __ldg(&yv[(size_t)i0 * 32 + lane]));
        a1 = f4add(a1, __ldg(&yv[(size_t)i1 * 32 + lane]));
        a2 = f4add(a2, __ldg(&yv[(size_t)i2 * 32 + lane]));
        a3 = f4add(a3, __ldg(&yv[(size_t)i3 * 32 + lane]));
    }
    for (; i < e; i++) {
        int ix = g_csr[i];
        a0 = f4add(a0, __ldg(&yv[(size_t)ix * 32 + lane]));
    }
    float4 a = f4add(f4add(a0, a1), f4add(a2, a3));

    const float d = g_dinv[row];
    float4 b4 = __ldg((const float4*)(bias + lane * 4));
    float4 o = make_float4(fmaxf(a.x * d + b4.x, 0.f),
                           fmaxf(a.y * d + b4.y, 0.f),
                           fmaxf(a.z * d + b4.z, 0.f),
                           fmaxf(a.w * d + b4.w, 0.f));
    *(float4*)(g_h + (size_t)row * 128 + lane * 4) = o;
}

// ---------------- launch ----------------------------------------------------
extern "C" void kernel_launch(void* const* d_in, const int* in_sizes, int n_in,
                              void* d_out, int out_size)
{
    const float* x      = (const float*)d_in[0];
    const int*   ei     = (const int*)d_in[1];   // int32 expected (JAX x64 off)
    const float* action = (const float*)d_in[2];
    const float* g1w    = (const float*)d_in[3];
    const float* g1b    = (const float*)d_in[4];
    const float* g2w    = (const float*)d_in[5];
    const float* g2b    = (const float*)d_in[6];
    const float* f1w    = (const float*)d_in[7];
    const float* f1b    = (const float*)d_in[8];
    const float* f2w    = (const float*)d_in[9];
    const float* f2b    = (const float*)d_in[10];
    float*       q      = (float*)d_out;

    const int gemm_grid = (N_NODES + 63) / 64;
    const int agg_grid  = (N_NODES + 7) / 8;

    // CSR build + dinv
    k_detect<<<1, 32>>>(ei);
    k_init<<<(N_NODES + 1023) / 1024, 1024>>>();
    k_hist<<<(N_EDGES + 255) / 256, 256>>>(ei);
    k_scan1<<<SCAN_BLOCKS, 1024>>>();
    k_scan2<<<1, 32>>>();
    k_scan3<<<SCAN_BLOCKS, 1024>>>();
    k_fill<<<(N_EDGES + 255) / 256, 256>>>(ei);

    // Layer 1: g_y = (x @ W1) * dinv ; g_h = relu(dinv*(y_self + sum y[src]) + b1)
    k_gemm<0, 0, 32><<<gemm_grid, 256>>>(x, nullptr, g1w, nullptr, nullptr, nullptr, nullptr);
    k_aggregate<<<agg_grid, 256>>>(g1b);

    // Layer 2: g_y = (g_h @ W2) * dinv ; g_h = relu(...)
    k_gemm<1, 0, 32><<<gemm_grid, 256>>>(nullptr, nullptr, g2w, nullptr, nullptr, nullptr, nullptr);
    k_aggregate<<<agg_grid, 256>>>(g2b);

    // FC head: relu([g_h|action] @ fc1 + b) . fc2 + b2  (fused)
    k_gemm<1, 1, 36><<<gemm_grid, 256>>>(nullptr, action, f1w, f1b, f2w, f2b, q);
}